// round 1
// baseline (speedup 1.0000x reference)
#include <cuda_runtime.h>

#define BATCH 4
#define SEQ   4096
#define DIM   768

// Scratch (allocation-free rule: __device__ globals)
__device__ float g_Q[(size_t)BATCH * SEQ * DIM];   // 48 MB
__device__ float g_K[(size_t)BATCH * SEQ * DIM];   // 48 MB
__device__ float g_V[(size_t)BATCH * SEQ * DIM];   // 48 MB
__device__ float g_P[(size_t)BATCH * SEQ * SEQ];   // 256 MB (scores -> probs in place)

#define BM 128
#define BN 128
#define BK 8
#define TM 8
#define TN 8
// 256 threads: 16x16 thread grid, each 8x8 microtile

// ---------------------------------------------------------------------------
// Stage 1: QKV projection. Y[16384 x 768] = X * W{q,k,v}, blockIdx.z selects W.
// ---------------------------------------------------------------------------
__global__ void __launch_bounds__(256, 2)
proj_kernel(const float* __restrict__ X,
            const float* __restrict__ Wq,
            const float* __restrict__ Wk,
            const float* __restrict__ Wv)
{
    const float* W = (blockIdx.z == 0) ? Wq : (blockIdx.z == 1) ? Wk : Wv;
    float* Y       = (blockIdx.z == 0) ? g_Q : (blockIdx.z == 1) ? g_K : g_V;

    const int i0 = blockIdx.y * BM;
    const int j0 = blockIdx.x * BN;

    __shared__ float As[BK][BM];
    __shared__ float Bs[BK][BN];

    float acc[TM][TN] = {};
    const int tid  = threadIdx.x;
    const int arow = tid >> 1, acol = (tid & 1) * 4;   // A: 128 rows x 8 k-cols
    const int brow = tid >> 5, bcol = (tid & 31) * 4;  // B: 8 k-rows x 128 cols
    const int ty   = tid >> 4, tx   = tid & 15;

    for (int kt = 0; kt < DIM; kt += BK) {
        float4 av = *reinterpret_cast<const float4*>(
            X + (size_t)(i0 + arow) * DIM + kt + acol);
        As[acol + 0][arow] = av.x;
        As[acol + 1][arow] = av.y;
        As[acol + 2][arow] = av.z;
        As[acol + 3][arow] = av.w;
        *reinterpret_cast<float4*>(&Bs[brow][bcol]) =
            *reinterpret_cast<const float4*>(W + (size_t)(kt + brow) * DIM + j0 + bcol);
        __syncthreads();

#pragma unroll
        for (int k = 0; k < BK; ++k) {
            float a[TM], b[TN];
#pragma unroll
            for (int i = 0; i < TM; ++i) a[i] = As[k][ty * TM + i];
#pragma unroll
            for (int j = 0; j < TN; ++j) b[j] = Bs[k][tx * TN + j];
#pragma unroll
            for (int i = 0; i < TM; ++i)
#pragma unroll
                for (int j = 0; j < TN; ++j)
                    acc[i][j] = fmaf(a[i], b[j], acc[i][j]);
        }
        __syncthreads();
    }

#pragma unroll
    for (int i = 0; i < TM; ++i) {
        float* yrow = Y + (size_t)(i0 + ty * TM + i) * DIM + j0 + tx * TN;
        reinterpret_cast<float4*>(yrow)[0] =
            make_float4(acc[i][0], acc[i][1], acc[i][2], acc[i][3]);
        reinterpret_cast<float4*>(yrow)[1] =
            make_float4(acc[i][4], acc[i][5], acc[i][6], acc[i][7]);
    }
}

// ---------------------------------------------------------------------------
// Stage 2: raw scores S = Q * K^T (per batch). Fully-masked 128x128 tiles
// (j0 > i0) are skipped entirely; garbage above the diagonal inside the
// diagonal tile is ignored by the softmax (it reads only k <= q).
// ---------------------------------------------------------------------------
__global__ void __launch_bounds__(256, 2)
scores_kernel()
{
    const int i0 = blockIdx.y * BM;
    const int j0 = blockIdx.x * BN;
    if (j0 > i0) return;  // tile entirely above the causal diagonal

    const int b = blockIdx.z;
    const float* Q  = g_Q + (size_t)b * SEQ * DIM;
    const float* Kp = g_K + (size_t)b * SEQ * DIM;
    float* P        = g_P + (size_t)b * SEQ * SEQ;

    __shared__ float As[BK][BM];
    __shared__ float Bs[BK][BN];

    float acc[TM][TN] = {};
    const int tid  = threadIdx.x;
    const int arow = tid >> 1, acol = (tid & 1) * 4;
    const int ty   = tid >> 4, tx   = tid & 15;

    for (int kt = 0; kt < DIM; kt += BK) {
        float4 av = *reinterpret_cast<const float4*>(
            Q + (size_t)(i0 + arow) * DIM + kt + acol);
        As[acol + 0][arow] = av.x;
        As[acol + 1][arow] = av.y;
        As[acol + 2][arow] = av.z;
        As[acol + 3][arow] = av.w;
        // K tile loaded exactly like A (NT gemm): Bs[k][n] = K[j0+n][kt+k]
        float4 bv = *reinterpret_cast<const float4*>(
            Kp + (size_t)(j0 + arow) * DIM + kt + acol);
        Bs[acol + 0][arow] = bv.x;
        Bs[acol + 1][arow] = bv.y;
        Bs[acol + 2][arow] = bv.z;
        Bs[acol + 3][arow] = bv.w;
        __syncthreads();

#pragma unroll
        for (int k = 0; k < BK; ++k) {
            float a[TM], b2[TN];
#pragma unroll
            for (int i = 0; i < TM; ++i) a[i] = As[k][ty * TM + i];
#pragma unroll
            for (int j = 0; j < TN; ++j) b2[j] = Bs[k][tx * TN + j];
#pragma unroll
            for (int i = 0; i < TM; ++i)
#pragma unroll
                for (int j = 0; j < TN; ++j)
                    acc[i][j] = fmaf(a[i], b2[j], acc[i][j]);
        }
        __syncthreads();
    }

#pragma unroll
    for (int i = 0; i < TM; ++i) {
        float* prow = P + (size_t)(i0 + ty * TM + i) * SEQ + j0 + tx * TN;
        reinterpret_cast<float4*>(prow)[0] =
            make_float4(acc[i][0], acc[i][1], acc[i][2], acc[i][3]);
        reinterpret_cast<float4*>(prow)[1] =
            make_float4(acc[i][4], acc[i][5], acc[i][6], acc[i][7]);
    }
}

// ---------------------------------------------------------------------------
// Stage 3: row softmax over k <= q (scaled by 1/sqrt(768)), in place.
// Also zero-fills (q, tile_end) inside the diagonal 128-tile so stage 4 can
// run rectangular k-loops to the tile boundary.
// ---------------------------------------------------------------------------
__global__ void __launch_bounds__(256)
softmax_kernel()
{
    const int row = blockIdx.x;         // 0 .. BATCH*SEQ-1
    const int b   = row >> 12;          // / 4096
    const int q   = row & (SEQ - 1);
    float* P = g_P + (size_t)b * SEQ * SEQ + (size_t)q * SEQ;
    const int len = q + 1;

    __shared__ float buf[SEQ];
    __shared__ float red[256];
    const int tid = threadIdx.x;
    const float scale = 0.03608439182435161f;  // 1/sqrt(768)

    float lmax = -1e30f;
    for (int i = tid; i < len; i += 256) {
        float v = P[i] * scale;
        buf[i] = v;
        lmax = fmaxf(lmax, v);
    }
    red[tid] = lmax;
    __syncthreads();
    for (int s = 128; s > 0; s >>= 1) {
        if (tid < s) red[tid] = fmaxf(red[tid], red[tid + s]);
        __syncthreads();
    }
    const float m = red[0];
    __syncthreads();

    float lsum = 0.f;
    for (int i = tid; i < len; i += 256) {
        float e = expf(buf[i] - m);
        buf[i] = e;
        lsum += e;
    }
    red[tid] = lsum;
    __syncthreads();
    for (int s = 128; s > 0; s >>= 1) {
        if (tid < s) red[tid] += red[tid + s];
        __syncthreads();
    }
    const float inv = 1.0f / red[0];

    for (int i = tid; i < len; i += 256) P[i] = buf[i] * inv;

    // zero pad to the end of this row's 128-wide diagonal tile
    const int zend = ((q >> 7) + 1) << 7;
    for (int i = len + tid; i < zend; i += 256) P[i] = 0.0f;
}

// ---------------------------------------------------------------------------
// Stage 4: O = P * V (per batch). K-loop bounded at the query tile's end
// (causal): rows [i0, i0+127] never attend beyond k = i0+127.
// ---------------------------------------------------------------------------
__global__ void __launch_bounds__(256, 2)
pv_kernel(float* __restrict__ Out)
{
    const int b  = blockIdx.z;
    const int i0 = blockIdx.y * BM;
    const int j0 = blockIdx.x * BN;   // over DIM=768

    const float* P = g_P + (size_t)b * SEQ * SEQ;
    const float* V = g_V + (size_t)b * SEQ * DIM;
    float* O       = Out + (size_t)b * SEQ * DIM;

    __shared__ float As[BK][BM];
    __shared__ float Bs[BK][BN];

    float acc[TM][TN] = {};
    const int tid  = threadIdx.x;
    const int arow = tid >> 1, acol = (tid & 1) * 4;
    const int brow = tid >> 5, bcol = (tid & 31) * 4;
    const int ty   = tid >> 4, tx   = tid & 15;

    const int kend = i0 + BM;  // causal bound (softmax zero-padded the tail)

    for (int kt = 0; kt < kend; kt += BK) {
        float4 av = *reinterpret_cast<const float4*>(
            P + (size_t)(i0 + arow) * SEQ + kt + acol);
        As[acol + 0][arow] = av.x;
        As[acol + 1][arow] = av.y;
        As[acol + 2][arow] = av.z;
        As[acol + 3][arow] = av.w;
        *reinterpret_cast<float4*>(&Bs[brow][bcol]) =
            *reinterpret_cast<const float4*>(V + (size_t)(kt + brow) * DIM + j0 + bcol);
        __syncthreads();

#pragma unroll
        for (int k = 0; k < BK; ++k) {
            float a[TM], b2[TN];
#pragma unroll
            for (int i = 0; i < TM; ++i) a[i] = As[k][ty * TM + i];
#pragma unroll
            for (int j = 0; j < TN; ++j) b2[j] = Bs[k][tx * TN + j];
#pragma unroll
            for (int i = 0; i < TM; ++i)
#pragma unroll
                for (int j = 0; j < TN; ++j)
                    acc[i][j] = fmaf(a[i], b2[j], acc[i][j]);
        }
        __syncthreads();
    }

#pragma unroll
    for (int i = 0; i < TM; ++i) {
        float* orow = O + (size_t)(i0 + ty * TM + i) * DIM + j0 + tx * TN;
        reinterpret_cast<float4*>(orow)[0] =
            make_float4(acc[i][0], acc[i][1], acc[i][2], acc[i][3]);
        reinterpret_cast<float4*>(orow)[1] =
            make_float4(acc[i][4], acc[i][5], acc[i][6], acc[i][7]);
    }
}

// ---------------------------------------------------------------------------
extern "C" void kernel_launch(void* const* d_in, const int* in_sizes, int n_in,
                              void* d_out, int out_size)
{
    const float* x  = (const float*)d_in[0];
    const float* Wq = (const float*)d_in[1];
    const float* Wk = (const float*)d_in[2];
    const float* Wv = (const float*)d_in[3];
    float* out = (float*)d_out;

    dim3 blk(256);
    // Stage 1: QKV (z selects Wq/Wk/Wv)
    proj_kernel<<<dim3(DIM / BN, (BATCH * SEQ) / BM, 3), blk>>>(x, Wq, Wk, Wv);
    // Stage 2: causal-pruned scores
    scores_kernel<<<dim3(SEQ / BN, SEQ / BM, BATCH), blk>>>();
    // Stage 3: row softmax
    softmax_kernel<<<dim3(BATCH * SEQ), blk>>>();
    // Stage 4: P * V -> output
    pv_kernel<<<dim3(DIM / BN, SEQ / BM, BATCH), blk>>>(out);
}

// round 3
// speedup vs baseline: 2.1035x; 2.1035x over previous
#include <cuda_runtime.h>
#include <cuda_bf16.h>
#include <cstdint>

#define BATCH 4
#define SEQ   4096
#define DIM   768
#define NTOK  (BATCH*SEQ)

// ---------------- scratch (__device__ globals: allocation-free rule) --------
__device__ float g_Q [(size_t)NTOK * DIM];        // 48 MB
__device__ float g_K [(size_t)NTOK * DIM];        // 48 MB
__device__ float g_V [(size_t)NTOK * DIM];        // 48 MB
__device__ float g_VT[(size_t)BATCH * DIM * SEQ]; // 48 MB  V^T per batch
__device__ float g_WT[3ull * DIM * DIM];          // 7 MB   W^T x3
__device__ float g_P [(size_t)BATCH * SEQ * SEQ]; // 256 MB scores->probs

// ---------------- warp MMA helpers (arch-agnostic PTX, sm_80+) --------------
__device__ __forceinline__ uint32_t smem_u32(const void* p) {
    uint32_t a;
    asm("{ .reg .u64 t; cvta.to.shared.u64 t, %1; cvt.u32.u64 %0, t; }"
        : "=r"(a) : "l"(p));
    return a;
}
__device__ __forceinline__ void ldsm_x4(uint32_t* r, uint32_t addr) {
    asm volatile("ldmatrix.sync.aligned.m8n8.x4.shared.b16 {%0,%1,%2,%3}, [%4];"
                 : "=r"(r[0]), "=r"(r[1]), "=r"(r[2]), "=r"(r[3]) : "r"(addr));
}
__device__ __forceinline__ void mma16816(float* d, const uint32_t* a, const uint32_t* b) {
    asm volatile(
        "mma.sync.aligned.m16n8k16.row.col.f32.bf16.bf16.f32 "
        "{%0,%1,%2,%3}, {%4,%5,%6,%7}, {%8,%9}, {%0,%1,%2,%3};"
        : "+f"(d[0]), "+f"(d[1]), "+f"(d[2]), "+f"(d[3])
        : "r"(a[0]), "r"(a[1]), "r"(a[2]), "r"(a[3]), "r"(b[0]), "r"(b[1]));
}

// split fp32 -> bf16 hi + bf16 lo (lo = bf16(x - hi)); 4 lanes packed
__device__ __forceinline__ void cvt_split(float4 v, uint2& hi, uint2& lo) {
    __nv_bfloat162 h01 = __float22bfloat162_rn(make_float2(v.x, v.y));
    __nv_bfloat162 h23 = __float22bfloat162_rn(make_float2(v.z, v.w));
    float2 f01 = __bfloat1622float2(h01);
    float2 f23 = __bfloat1622float2(h23);
    __nv_bfloat162 l01 = __float22bfloat162_rn(make_float2(v.x - f01.x, v.y - f01.y));
    __nv_bfloat162 l23 = __float22bfloat162_rn(make_float2(v.z - f23.x, v.w - f23.y));
    hi.x = *reinterpret_cast<uint32_t*>(&h01);
    hi.y = *reinterpret_cast<uint32_t*>(&h23);
    lo.x = *reinterpret_cast<uint32_t*>(&l01);
    lo.y = *reinterpret_cast<uint32_t*>(&l23);
}

// ---------------- GEMM core: C[128,128](+=/=) A[M,K] * B[N,K]^T -------------
// 256 threads, 8 warps in 2(m) x 4(n); warp tile 64x32; k-step 32.
#define LDS 40   // padded smem row stride (bf16 units): conflict-free ldmatrix

__device__ __forceinline__ void gemm_core(
    const float* __restrict__ A, int lda,
    const float* __restrict__ B, int ldb,
    float* __restrict__ C, int ldc,
    int i0, int j0, int K)
{
    __shared__ __align__(16) uint16_t sAhi[128 * LDS];
    __shared__ __align__(16) uint16_t sAlo[128 * LDS];
    __shared__ __align__(16) uint16_t sBhi[128 * LDS];
    __shared__ __align__(16) uint16_t sBlo[128 * LDS];

    const int tid  = threadIdx.x;
    const int wid  = tid >> 5;
    const int lane = tid & 31;
    const int m0 = (wid & 1) * 64;        // warp row offset
    const int n0 = (wid >> 1) * 32;       // warp col offset

    const uint32_t bAhi = smem_u32(sAhi);
    const uint32_t bAlo = smem_u32(sAlo);
    const uint32_t bBhi = smem_u32(sBhi);
    const uint32_t bBlo = smem_u32(sBlo);

    // ldmatrix lane->address precomputation
    const int a_row = lane & 15;                 // 16 rows
    const int a_col = (lane >> 4) * 8;           // k half
    const int b_row = ((lane >> 4) & 1) * 8 + (lane & 7);  // n within 16
    const int b_col = ((lane >> 3) & 1) * 8;     // k half

    float acc[4][4][4] = {};

    for (int kt = 0; kt < K; kt += 32) {
        // ---- stage 128x32 fp32 of A and B, split to bf16 hi/lo --------------
#pragma unroll
        for (int it = 0; it < 4; ++it) {
            int u  = it * 256 + tid;     // 0..1023
            int r  = u >> 3;             // 0..127
            int c4 = (u & 7) * 4;        // 0..28
            uint2 hi, lo;
            float4 va = *reinterpret_cast<const float4*>(
                A + (size_t)(i0 + r) * lda + kt + c4);
            cvt_split(va, hi, lo);
            *reinterpret_cast<uint2*>(&sAhi[r * LDS + c4]) = hi;
            *reinterpret_cast<uint2*>(&sAlo[r * LDS + c4]) = lo;
            float4 vb = *reinterpret_cast<const float4*>(
                B + (size_t)(j0 + r) * ldb + kt + c4);
            cvt_split(vb, hi, lo);
            *reinterpret_cast<uint2*>(&sBhi[r * LDS + c4]) = hi;
            *reinterpret_cast<uint2*>(&sBlo[r * LDS + c4]) = lo;
        }
        __syncthreads();

        // ---- MMA phase: 2 k16 slices, 3 split passes each -------------------
#pragma unroll
        for (int kk = 0; kk < 32; kk += 16) {
            uint32_t aH[4][4], aL[4][4], bH[4][2], bL[4][2];
#pragma unroll
            for (int mi = 0; mi < 4; ++mi) {
                uint32_t off = (uint32_t)((m0 + mi * 16 + a_row) * LDS + kk + a_col) * 2;
                ldsm_x4(aH[mi], bAhi + off);
                ldsm_x4(aL[mi], bAlo + off);
            }
#pragma unroll
            for (int nj = 0; nj < 2; ++nj) {
                uint32_t off = (uint32_t)((n0 + nj * 16 + b_row) * LDS + kk + b_col) * 2;
                uint32_t r4[4];
                ldsm_x4(r4, bBhi + off);
                bH[nj * 2][0] = r4[0]; bH[nj * 2][1] = r4[1];
                bH[nj * 2 + 1][0] = r4[2]; bH[nj * 2 + 1][1] = r4[3];
                ldsm_x4(r4, bBlo + off);
                bL[nj * 2][0] = r4[0]; bL[nj * 2][1] = r4[1];
                bL[nj * 2 + 1][0] = r4[2]; bL[nj * 2 + 1][1] = r4[3];
            }
#pragma unroll
            for (int mi = 0; mi < 4; ++mi)
#pragma unroll
                for (int nj = 0; nj < 4; ++nj) {
                    mma16816(acc[mi][nj], aH[mi], bH[nj]);  // hi*hi
                    mma16816(acc[mi][nj], aH[mi], bL[nj]);  // hi*lo
                    mma16816(acc[mi][nj], aL[mi], bH[nj]);  // lo*hi
                }
        }
        __syncthreads();
    }

    // ---- epilogue: D frag -> global ----------------------------------------
    const int tr = lane >> 2;
    const int tc = (lane & 3) * 2;
#pragma unroll
    for (int mi = 0; mi < 4; ++mi)
#pragma unroll
        for (int nj = 0; nj < 4; ++nj) {
            int row = i0 + m0 + mi * 16 + tr;
            int col = j0 + n0 + nj * 8 + tc;
            *reinterpret_cast<float2*>(C + (size_t)row * ldc + col) =
                make_float2(acc[mi][nj][0], acc[mi][nj][1]);
            *reinterpret_cast<float2*>(C + (size_t)(row + 8) * ldc + col) =
                make_float2(acc[mi][nj][2], acc[mi][nj][3]);
        }
}

// ---------------- GEMM stage kernels ----------------------------------------
__global__ void __launch_bounds__(256, 1)
proj_tc(const float* __restrict__ X)
{
    const float* Bm = g_WT + (size_t)blockIdx.z * DIM * DIM;
    float* C = (blockIdx.z == 0) ? g_Q : (blockIdx.z == 1) ? g_K : g_V;
    gemm_core(X, DIM, Bm, DIM, C, DIM, blockIdx.y * 128, blockIdx.x * 128, DIM);
}

__global__ void __launch_bounds__(256, 1)
scores_tc()
{
    const int i0 = blockIdx.y * 128, j0 = blockIdx.x * 128;
    if (j0 > i0) return;   // fully-masked causal tile
    const float* A  = g_Q + (size_t)blockIdx.z * SEQ * DIM;
    const float* Bm = g_K + (size_t)blockIdx.z * SEQ * DIM;
    float* C        = g_P + (size_t)blockIdx.z * SEQ * SEQ;
    gemm_core(A, DIM, Bm, DIM, C, SEQ, i0, j0, DIM);
}

__global__ void __launch_bounds__(256, 1)
pv_tc(float* __restrict__ out)
{
    const int i0 = blockIdx.y * 128, j0 = blockIdx.x * 128;
    const float* A  = g_P  + (size_t)blockIdx.z * SEQ * SEQ;
    const float* Bm = g_VT + (size_t)blockIdx.z * DIM * SEQ;
    float* C        = out  + (size_t)blockIdx.z * SEQ * DIM;
    gemm_core(A, SEQ, Bm, SEQ, C, DIM, i0, j0, i0 + 128);  // causal K bound
}

// ---------------- transposes -------------------------------------------------
__device__ __forceinline__ void transpose_body(const float* __restrict__ src,
                                               float* __restrict__ dst,
                                               int R, int Ccols)
{
    __shared__ float t[32][33];
    const int bx = blockIdx.x * 32, by = blockIdx.y * 32;
    const int tx = threadIdx.x, ty = threadIdx.y;
#pragma unroll
    for (int j = 0; j < 32; j += 8)
        t[ty + j][tx] = src[(size_t)(by + ty + j) * Ccols + bx + tx];
    __syncthreads();
#pragma unroll
    for (int j = 0; j < 32; j += 8)
        dst[(size_t)(bx + ty + j) * R + by + tx] = t[tx][ty + j];
}

__global__ void transpose_w(const float* __restrict__ Wq,
                            const float* __restrict__ Wk,
                            const float* __restrict__ Wv)
{
    const float* src = (blockIdx.z == 0) ? Wq : (blockIdx.z == 1) ? Wk : Wv;
    float* dst = g_WT + (size_t)blockIdx.z * DIM * DIM;
    transpose_body(src, dst, DIM, DIM);
}

__global__ void transpose_v()
{
    const int b = blockIdx.z;
    transpose_body(g_V + (size_t)b * SEQ * DIM, g_VT + (size_t)b * DIM * SEQ,
                   SEQ, DIM);
}

// ---------------- softmax (unchanged, proven) ---------------------------------
__global__ void __launch_bounds__(256)
softmax_kernel()
{
    const int row = blockIdx.x;
    const int b   = row >> 12;
    const int q   = row & (SEQ - 1);
    float* P = g_P + (size_t)b * SEQ * SEQ + (size_t)q * SEQ;
    const int len = q + 1;

    __shared__ float buf[SEQ];
    __shared__ float red[256];
    const int tid = threadIdx.x;
    const float scale = 0.03608439182435161f;  // 1/sqrt(768)

    float lmax = -1e30f;
    for (int i = tid; i < len; i += 256) {
        float v = P[i] * scale;
        buf[i] = v;
        lmax = fmaxf(lmax, v);
    }
    red[tid] = lmax;
    __syncthreads();
    for (int s = 128; s > 0; s >>= 1) {
        if (tid < s) red[tid] = fmaxf(red[tid], red[tid + s]);
        __syncthreads();
    }
    const float m = red[0];
    __syncthreads();

    float lsum = 0.f;
    for (int i = tid; i < len; i += 256) {
        float e = expf(buf[i] - m);
        buf[i] = e;
        lsum += e;
    }
    red[tid] = lsum;
    __syncthreads();
    for (int s = 128; s > 0; s >>= 1) {
        if (tid < s) red[tid] += red[tid + s];
        __syncthreads();
    }
    const float inv = 1.0f / red[0];

    for (int i = tid; i < len; i += 256) P[i] = buf[i] * inv;

    const int zend = ((q >> 7) + 1) << 7;   // zero-pad to 128-tile boundary
    for (int i = len + tid; i < zend; i += 256) P[i] = 0.0f;
}

// ---------------- launch -------------------------------------------------------
extern "C" void kernel_launch(void* const* d_in, const int* in_sizes, int n_in,
                              void* d_out, int out_size)
{
    const float* x  = (const float*)d_in[0];
    const float* Wq = (const float*)d_in[1];
    const float* Wk = (const float*)d_in[2];
    const float* Wv = (const float*)d_in[3];
    float* out = (float*)d_out;

    dim3 t32(32, 8);
    transpose_w<<<dim3(DIM / 32, DIM / 32, 3), t32>>>(Wq, Wk, Wv);
    proj_tc<<<dim3(DIM / 128, NTOK / 128, 3), 256>>>(x);
    transpose_v<<<dim3(DIM / 32, SEQ / 32, BATCH), t32>>>();
    scores_tc<<<dim3(SEQ / 128, SEQ / 128, BATCH), 256>>>();
    softmax_kernel<<<BATCH * SEQ, 256>>>();
    pv_tc<<<dim3(DIM / 128, SEQ / 128, BATCH), 256>>>(out);
}

// round 4
// speedup vs baseline: 2.8450x; 1.3525x over previous
#include <cuda_runtime.h>
#include <cuda_bf16.h>
#include <cstdint>

#define BATCH 4
#define SEQ   4096
#define DIM   768
#define NTOK  (BATCH*SEQ)

// ---------------- scratch (__device__ globals: allocation-free rule) --------
__device__ __nv_bfloat16 g_Xhi [(size_t)NTOK * DIM];
__device__ __nv_bfloat16 g_Xlo [(size_t)NTOK * DIM];
__device__ __nv_bfloat16 g_WThi[3ull * DIM * DIM];
__device__ __nv_bfloat16 g_WTlo[3ull * DIM * DIM];
__device__ __nv_bfloat16 g_Qhi [(size_t)NTOK * DIM];
__device__ __nv_bfloat16 g_Qlo [(size_t)NTOK * DIM];
__device__ __nv_bfloat16 g_Khi [(size_t)NTOK * DIM];
__device__ __nv_bfloat16 g_Klo [(size_t)NTOK * DIM];
__device__ __nv_bfloat16 g_Vhi [(size_t)NTOK * DIM];
__device__ __nv_bfloat16 g_Vlo [(size_t)NTOK * DIM];
__device__ __nv_bfloat16 g_VThi[(size_t)BATCH * DIM * SEQ];
__device__ __nv_bfloat16 g_VTlo[(size_t)BATCH * DIM * SEQ];
__device__ float         g_P   [(size_t)BATCH * SEQ * SEQ];   // raw scores (fp32)
__device__ __nv_bfloat16 g_Phi [(size_t)BATCH * SEQ * SEQ];   // probs hi
__device__ __nv_bfloat16 g_Plo [(size_t)BATCH * SEQ * SEQ];   // probs lo

// ---------------- PTX helpers (arch-agnostic, sm_80-class) ------------------
__device__ __forceinline__ uint32_t smem_u32(const void* p) {
    uint32_t a;
    asm("{ .reg .u64 t; cvta.to.shared.u64 t, %1; cvt.u32.u64 %0, t; }"
        : "=r"(a) : "l"(p));
    return a;
}
__device__ __forceinline__ void cp16(uint32_t dst, const void* src) {
    asm volatile("cp.async.cg.shared.global [%0], [%1], 16;"
                 :: "r"(dst), "l"(src) : "memory");
}
#define CP_COMMIT() asm volatile("cp.async.commit_group;" ::: "memory")
#define CP_WAIT(N)  asm volatile("cp.async.wait_group %0;" :: "n"(N) : "memory")

__device__ __forceinline__ void ldsm_x4(uint32_t* r, uint32_t addr) {
    asm volatile("ldmatrix.sync.aligned.m8n8.x4.shared.b16 {%0,%1,%2,%3}, [%4];"
                 : "=r"(r[0]), "=r"(r[1]), "=r"(r[2]), "=r"(r[3]) : "r"(addr));
}
__device__ __forceinline__ void mma16816(float* d, const uint32_t* a, const uint32_t* b) {
    asm volatile(
        "mma.sync.aligned.m16n8k16.row.col.f32.bf16.bf16.f32 "
        "{%0,%1,%2,%3}, {%4,%5,%6,%7}, {%8,%9}, {%0,%1,%2,%3};"
        : "+f"(d[0]), "+f"(d[1]), "+f"(d[2]), "+f"(d[3])
        : "r"(a[0]), "r"(a[1]), "r"(a[2]), "r"(a[3]), "r"(b[0]), "r"(b[1]));
}

// fp32 pair -> bf16 hi pair + bf16 lo pair (packed u32 each)
__device__ __forceinline__ void split2(float a, float b, uint32_t& h, uint32_t& l) {
    __nv_bfloat162 hv = __float22bfloat162_rn(make_float2(a, b));
    float2 f = __bfloat1622float2(hv);
    __nv_bfloat162 lv = __float22bfloat162_rn(make_float2(a - f.x, b - f.y));
    h = *reinterpret_cast<uint32_t*>(&hv);
    l = *reinterpret_cast<uint32_t*>(&lv);
}

// ---------------- pipelined GEMM core ----------------------------------------
// C[128,128] = A[128,K](hi+lo) * B[128,K](hi+lo)^T, bf16 MMA x3, fp32 accum.
// 256 threads, warp grid 2(m) x 4(n), warp tile 64x32, k-step 32, 2-stage cp.async.
#define LDSE 40                      // smem row stride in bf16 elems (80 B)
#define BUFB (128 * LDSE * 2)        // 10240 B per buffer
#define SMEM_BYTES (2 * 4 * BUFB)    // 81920 B

// MODE 0: write fp32 C.  MODE 1: write split bf16 Chi/Clo.
template <int MODE>
__device__ __forceinline__ void gemm_pipe(
    const __nv_bfloat16* __restrict__ Ahi, const __nv_bfloat16* __restrict__ Alo, int lda,
    const __nv_bfloat16* __restrict__ Bhi, const __nv_bfloat16* __restrict__ Blo, int ldb,
    float* __restrict__ C, __nv_bfloat16* __restrict__ Chi, __nv_bfloat16* __restrict__ Clo,
    int ldc, int i0, int j0, int K)
{
    extern __shared__ __align__(16) uint16_t dsm[];
    const uint32_t sb = smem_u32(dsm);

    const int tid  = threadIdx.x;
    const int wid  = tid >> 5;
    const int lane = tid & 31;
    const int m0 = (wid & 1) * 64;
    const int n0 = (wid >> 1) * 32;

    // ldmatrix lane addressing (validated in R3)
    const int a_row = lane & 15;
    const int a_col = (lane >> 4) * 8;
    const int b_row = ((lane >> 4) & 1) * 8 + (lane & 7);
    const int b_col = ((lane >> 3) & 1) * 8;

    // cp.async chunk mapping: 2 chunks/thread/buffer (128 rows x 4 x 16B)
    const int r0 = tid >> 2,        c0 = (tid & 3) * 8;          // chunk 0
    const int r1 = (tid + 256) >> 2, c1 = ((tid + 256) & 3) * 8; // chunk 1

    const __nv_bfloat16* gsrc[4] = {Ahi, Alo, Bhi, Blo};
    const int glda[4] = {lda, lda, ldb, ldb};
    const int grow[4] = {i0, i0, j0, j0};

    const int nk = K >> 5;

    auto stage = [&](int s, int kt) {
#pragma unroll
        for (int b = 0; b < 4; ++b) {
            uint32_t base = sb + (uint32_t)((s * 4 + b) * BUFB);
            const __nv_bfloat16* g = gsrc[b];
            cp16(base + (uint32_t)(r0 * LDSE + c0) * 2,
                 g + (size_t)(grow[b] + r0) * glda[b] + kt + c0);
            cp16(base + (uint32_t)(r1 * LDSE + c1) * 2,
                 g + (size_t)(grow[b] + r1) * glda[b] + kt + c1);
        }
        CP_COMMIT();
    };

    float acc[4][4][4] = {};

    stage(0, 0);
    for (int it = 0; it < nk; ++it) {
        const int s = it & 1;
        if (it + 1 < nk) {
            stage(s ^ 1, (it + 1) << 5);
            CP_WAIT(1);
        } else {
            CP_WAIT(0);
        }
        __syncthreads();

        const uint32_t bAhi = sb + (uint32_t)((s * 4 + 0) * BUFB);
        const uint32_t bAlo = sb + (uint32_t)((s * 4 + 1) * BUFB);
        const uint32_t bBhi = sb + (uint32_t)((s * 4 + 2) * BUFB);
        const uint32_t bBlo = sb + (uint32_t)((s * 4 + 3) * BUFB);

#pragma unroll
        for (int kk = 0; kk < 32; kk += 16) {
            uint32_t aH[4][4], aL[4][4];
#pragma unroll
            for (int mi = 0; mi < 4; ++mi) {
                uint32_t off = (uint32_t)((m0 + mi * 16 + a_row) * LDSE + kk + a_col) * 2;
                ldsm_x4(aH[mi], bAhi + off);
                ldsm_x4(aL[mi], bAlo + off);
            }
#pragma unroll
            for (int nj = 0; nj < 2; ++nj) {
                uint32_t off = (uint32_t)((n0 + nj * 16 + b_row) * LDSE + kk + b_col) * 2;
                uint32_t bh[4], bl[4];
                ldsm_x4(bh, bBhi + off);
                ldsm_x4(bl, bBlo + off);
#pragma unroll
                for (int mi = 0; mi < 4; ++mi) {
                    mma16816(acc[mi][nj * 2],     aH[mi], bh);
                    mma16816(acc[mi][nj * 2 + 1], aH[mi], bh + 2);
                    mma16816(acc[mi][nj * 2],     aH[mi], bl);
                    mma16816(acc[mi][nj * 2 + 1], aH[mi], bl + 2);
                    mma16816(acc[mi][nj * 2],     aL[mi], bh);
                    mma16816(acc[mi][nj * 2 + 1], aL[mi], bh + 2);
                }
            }
        }
        __syncthreads();   // all warps done reading stage s before it is rewritten
    }

    // ---- epilogue ------------------------------------------------------------
    const int tr = lane >> 2;
    const int tc = (lane & 3) * 2;
#pragma unroll
    for (int mi = 0; mi < 4; ++mi)
#pragma unroll
        for (int nj = 0; nj < 4; ++nj) {
            int row = i0 + m0 + mi * 16 + tr;
            int col = j0 + n0 + nj * 8 + tc;
            if (MODE == 0) {
                *reinterpret_cast<float2*>(C + (size_t)row * ldc + col) =
                    make_float2(acc[mi][nj][0], acc[mi][nj][1]);
                *reinterpret_cast<float2*>(C + (size_t)(row + 8) * ldc + col) =
                    make_float2(acc[mi][nj][2], acc[mi][nj][3]);
            } else {
                uint32_t h, l;
                size_t idx = (size_t)row * ldc + col;
                split2(acc[mi][nj][0], acc[mi][nj][1], h, l);
                *reinterpret_cast<uint32_t*>(Chi + idx) = h;
                *reinterpret_cast<uint32_t*>(Clo + idx) = l;
                idx = (size_t)(row + 8) * ldc + col;
                split2(acc[mi][nj][2], acc[mi][nj][3], h, l);
                *reinterpret_cast<uint32_t*>(Chi + idx) = h;
                *reinterpret_cast<uint32_t*>(Clo + idx) = l;
            }
        }
}

// ---------------- GEMM stage kernels ------------------------------------------
__global__ void __launch_bounds__(256, 2)
proj_tc()
{
    const int z = blockIdx.z;
    const __nv_bfloat16* Bh = g_WThi + (size_t)z * DIM * DIM;
    const __nv_bfloat16* Bl = g_WTlo + (size_t)z * DIM * DIM;
    __nv_bfloat16* Ch = (z == 0) ? g_Qhi : (z == 1) ? g_Khi : g_Vhi;
    __nv_bfloat16* Cl = (z == 0) ? g_Qlo : (z == 1) ? g_Klo : g_Vlo;
    gemm_pipe<1>(g_Xhi, g_Xlo, DIM, Bh, Bl, DIM,
                 nullptr, Ch, Cl, DIM, blockIdx.y * 128, blockIdx.x * 128, DIM);
}

__global__ void __launch_bounds__(256, 2)
scores_tc()
{
    const int i0 = blockIdx.y * 128, j0 = blockIdx.x * 128;
    if (j0 > i0) return;   // fully-masked causal tile
    const size_t off = (size_t)blockIdx.z * SEQ * DIM;
    float* C = g_P + (size_t)blockIdx.z * SEQ * SEQ;
    gemm_pipe<0>(g_Qhi + off, g_Qlo + off, DIM, g_Khi + off, g_Klo + off, DIM,
                 C, nullptr, nullptr, SEQ, i0, j0, DIM);
}

__global__ void __launch_bounds__(256, 2)
pv_tc(float* __restrict__ out)
{
    const int i0 = blockIdx.y * 128, j0 = blockIdx.x * 128;
    const size_t poff = (size_t)blockIdx.z * SEQ * SEQ;
    const size_t voff = (size_t)blockIdx.z * DIM * SEQ;
    float* C = out + (size_t)blockIdx.z * SEQ * DIM;
    gemm_pipe<0>(g_Phi + poff, g_Plo + poff, SEQ, g_VThi + voff, g_VTlo + voff, SEQ,
                 C, nullptr, nullptr, DIM, i0, j0, i0 + 128);   // causal K bound
}

// ---------------- conversion / transpose kernels -------------------------------
__global__ void conv_x(const float* __restrict__ X)
{
    size_t i = (size_t)blockIdx.x * blockDim.x + threadIdx.x;
    const size_t n4 = (size_t)NTOK * DIM / 4;
    for (; i < n4; i += (size_t)gridDim.x * blockDim.x) {
        float4 v = reinterpret_cast<const float4*>(X)[i];
        uint32_t h0, l0, h1, l1;
        split2(v.x, v.y, h0, l0);
        split2(v.z, v.w, h1, l1);
        reinterpret_cast<uint2*>(g_Xhi)[i] = make_uint2(h0, h1);
        reinterpret_cast<uint2*>(g_Xlo)[i] = make_uint2(l0, l1);
    }
}

__global__ void transpose_w(const float* __restrict__ Wq,
                            const float* __restrict__ Wk,
                            const float* __restrict__ Wv)
{
    const float* src = (blockIdx.z == 0) ? Wq : (blockIdx.z == 1) ? Wk : Wv;
    __nv_bfloat16* dh = g_WThi + (size_t)blockIdx.z * DIM * DIM;
    __nv_bfloat16* dl = g_WTlo + (size_t)blockIdx.z * DIM * DIM;
    __shared__ float t[32][33];
    const int bx = blockIdx.x * 32, by = blockIdx.y * 32;
    const int tx = threadIdx.x, ty = threadIdx.y;
#pragma unroll
    for (int j = 0; j < 32; j += 8)
        t[ty + j][tx] = src[(size_t)(by + ty + j) * DIM + bx + tx];
    __syncthreads();
#pragma unroll
    for (int j = 0; j < 32; j += 8) {
        float v = t[tx][ty + j];
        __nv_bfloat16 h = __float2bfloat16(v);
        size_t idx = (size_t)(bx + ty + j) * DIM + by + tx;
        dh[idx] = h;
        dl[idx] = __float2bfloat16(v - __bfloat162float(h));
    }
}

__global__ void transpose_v()
{
    const int b = blockIdx.z;
    const __nv_bfloat16* sh = g_Vhi + (size_t)b * SEQ * DIM;
    const __nv_bfloat16* sl = g_Vlo + (size_t)b * SEQ * DIM;
    __nv_bfloat16* dh = g_VThi + (size_t)b * DIM * SEQ;
    __nv_bfloat16* dl = g_VTlo + (size_t)b * DIM * SEQ;
    __shared__ float t[32][33];
    const int bx = blockIdx.x * 32, by = blockIdx.y * 32;   // bx over DIM, by over SEQ
    const int tx = threadIdx.x, ty = threadIdx.y;
#pragma unroll
    for (int j = 0; j < 32; j += 8) {
        size_t idx = (size_t)(by + ty + j) * DIM + bx + tx;
        t[ty + j][tx] = __bfloat162float(sh[idx]) + __bfloat162float(sl[idx]);
    }
    __syncthreads();
#pragma unroll
    for (int j = 0; j < 32; j += 8) {
        float v = t[tx][ty + j];
        __nv_bfloat16 h = __float2bfloat16(v);
        size_t idx = (size_t)(bx + ty + j) * SEQ + by + tx;
        dh[idx] = h;
        dl[idx] = __float2bfloat16(v - __bfloat162float(h));
    }
}

// ---------------- softmax: fp32 scores -> split bf16 probs ---------------------
__global__ void __launch_bounds__(256)
softmax_kernel()
{
    const int row = blockIdx.x;
    const int b   = row >> 12;
    const int q   = row & (SEQ - 1);
    const size_t base = (size_t)b * SEQ * SEQ + (size_t)q * SEQ;
    const float* P = g_P + base;
    __nv_bfloat16* Ph = g_Phi + base;
    __nv_bfloat16* Pl = g_Plo + base;
    const int len = q + 1;

    __shared__ float buf[SEQ];
    __shared__ float red[256];
    const int tid = threadIdx.x;
    const float scale = 0.03608439182435161f;  // 1/sqrt(768)

    float lmax = -1e30f;
    for (int i = tid; i < len; i += 256) {
        float v = P[i] * scale;
        buf[i] = v;
        lmax = fmaxf(lmax, v);
    }
    red[tid] = lmax;
    __syncthreads();
    for (int s = 128; s > 0; s >>= 1) {
        if (tid < s) red[tid] = fmaxf(red[tid], red[tid + s]);
        __syncthreads();
    }
    const float m = red[0];
    __syncthreads();

    float lsum = 0.f;
    for (int i = tid; i < len; i += 256) {
        float e = expf(buf[i] - m);
        buf[i] = e;
        lsum += e;
    }
    red[tid] = lsum;
    __syncthreads();
    for (int s = 128; s > 0; s >>= 1) {
        if (tid < s) red[tid] += red[tid + s];
        __syncthreads();
    }
    const float inv = 1.0f / red[0];

    for (int i = tid; i < len; i += 256) {
        float p = buf[i] * inv;
        __nv_bfloat16 h = __float2bfloat16(p);
        Ph[i] = h;
        Pl[i] = __float2bfloat16(p - __bfloat162float(h));
    }
    const int zend = ((q >> 7) + 1) << 7;   // zero-pad to 128-tile boundary
    for (int i = len + tid; i < zend; i += 256) {
        Ph[i] = __float2bfloat16(0.f);
        Pl[i] = __float2bfloat16(0.f);
    }
}

// ---------------- launch ---------------------------------------------------------
extern "C" void kernel_launch(void* const* d_in, const int* in_sizes, int n_in,
                              void* d_out, int out_size)
{
    const float* x  = (const float*)d_in[0];
    const float* Wq = (const float*)d_in[1];
    const float* Wk = (const float*)d_in[2];
    const float* Wv = (const float*)d_in[3];
    float* out = (float*)d_out;

    cudaFuncSetAttribute(proj_tc,   cudaFuncAttributeMaxDynamicSharedMemorySize, SMEM_BYTES);
    cudaFuncSetAttribute(scores_tc, cudaFuncAttributeMaxDynamicSharedMemorySize, SMEM_BYTES);
    cudaFuncSetAttribute(pv_tc,     cudaFuncAttributeMaxDynamicSharedMemorySize, SMEM_BYTES);

    dim3 t32(32, 8);
    conv_x<<<512, 256>>>(x);
    transpose_w<<<dim3(DIM / 32, DIM / 32, 3), t32>>>(Wq, Wk, Wv);
    proj_tc<<<dim3(DIM / 128, NTOK / 128, 3), 256, SMEM_BYTES>>>();
    transpose_v<<<dim3(DIM / 32, SEQ / 32, BATCH), t32>>>();
    scores_tc<<<dim3(SEQ / 128, SEQ / 128, BATCH), 256, SMEM_BYTES>>>();
    softmax_kernel<<<BATCH * SEQ, 256>>>();
    pv_tc<<<dim3(DIM / 128, SEQ / 128, BATCH), 256, SMEM_BYTES>>>(out);
}

// round 5
// speedup vs baseline: 2.9113x; 1.0233x over previous
#include <cuda_runtime.h>
#include <cuda_bf16.h>
#include <cstdint>

#define BATCH 4
#define SEQ   4096
#define DIM   768
#define NTOK  (BATCH*SEQ)

// ---------------- scratch (__device__ globals: allocation-free rule) --------
__device__ __nv_bfloat16 g_Xhi [(size_t)NTOK * DIM];
__device__ __nv_bfloat16 g_Xlo [(size_t)NTOK * DIM];
__device__ __nv_bfloat16 g_WThi[3ull * DIM * DIM];
__device__ __nv_bfloat16 g_WTlo[3ull * DIM * DIM];
__device__ __nv_bfloat16 g_Qhi [(size_t)NTOK * DIM];
__device__ __nv_bfloat16 g_Qlo [(size_t)NTOK * DIM];
__device__ __nv_bfloat16 g_Khi [(size_t)NTOK * DIM];
__device__ __nv_bfloat16 g_Klo [(size_t)NTOK * DIM];
__device__ __nv_bfloat16 g_Vhi [(size_t)NTOK * DIM];
__device__ __nv_bfloat16 g_Vlo [(size_t)NTOK * DIM];
__device__ __nv_bfloat16 g_VThi[(size_t)BATCH * DIM * SEQ];
__device__ __nv_bfloat16 g_VTlo[(size_t)BATCH * DIM * SEQ];
__device__ __nv_bfloat16 g_Phi [(size_t)BATCH * SEQ * SEQ];   // exp(scores) hi
__device__ __nv_bfloat16 g_Plo [(size_t)BATCH * SEQ * SEQ];   // exp(scores) lo
__device__ float g_partial[(size_t)NTOK * 32];                // per-(row,tile) exp sums
__device__ float g_rowsum [(size_t)NTOK];                     // final row sums

// ---------------- PTX helpers (arch-agnostic, sm_80-class) ------------------
__device__ __forceinline__ uint32_t smem_u32(const void* p) {
    uint32_t a;
    asm("{ .reg .u64 t; cvta.to.shared.u64 t, %1; cvt.u32.u64 %0, t; }"
        : "=r"(a) : "l"(p));
    return a;
}
__device__ __forceinline__ void cp16(uint32_t dst, const void* src) {
    asm volatile("cp.async.cg.shared.global [%0], [%1], 16;"
                 :: "r"(dst), "l"(src) : "memory");
}
#define CP_COMMIT() asm volatile("cp.async.commit_group;" ::: "memory")
#define CP_WAIT(N)  asm volatile("cp.async.wait_group %0;" :: "n"(N) : "memory")

__device__ __forceinline__ void ldsm_x4(uint32_t* r, uint32_t addr) {
    asm volatile("ldmatrix.sync.aligned.m8n8.x4.shared.b16 {%0,%1,%2,%3}, [%4];"
                 : "=r"(r[0]), "=r"(r[1]), "=r"(r[2]), "=r"(r[3]) : "r"(addr));
}
__device__ __forceinline__ void mma16816(float* d, const uint32_t* a, const uint32_t* b) {
    asm volatile(
        "mma.sync.aligned.m16n8k16.row.col.f32.bf16.bf16.f32 "
        "{%0,%1,%2,%3}, {%4,%5,%6,%7}, {%8,%9}, {%0,%1,%2,%3};"
        : "+f"(d[0]), "+f"(d[1]), "+f"(d[2]), "+f"(d[3])
        : "r"(a[0]), "r"(a[1]), "r"(a[2]), "r"(a[3]), "r"(b[0]), "r"(b[1]));
}

// fp32 pair -> bf16 hi pair + bf16 lo pair (packed u32 each)
__device__ __forceinline__ void split2(float a, float b, uint32_t& h, uint32_t& l) {
    __nv_bfloat162 hv = __float22bfloat162_rn(make_float2(a, b));
    float2 f = __bfloat1622float2(hv);
    __nv_bfloat162 lv = __float22bfloat162_rn(make_float2(a - f.x, b - f.y));
    h = *reinterpret_cast<uint32_t*>(&hv);
    l = *reinterpret_cast<uint32_t*>(&lv);
}

// ---------------- pipelined GEMM core ----------------------------------------
// C[128,128] = A[128,K](hi+lo) * B[128,K](hi+lo)^T, bf16 MMA x3, fp32 accum.
// 256 threads, warp grid 2(m) x 4(n), warp tile 64x32, k-step 32, 2-stage cp.async.
#define LDSE 40                      // smem row stride in bf16 elems (80 B)
#define BUFB (128 * LDSE * 2)        // 10240 B per buffer
#define SMEM_BYTES (2 * 4 * BUFB)    // 81920 B

#define SM_SCALE 0.03608439182435161f   // 1/sqrt(768)

// MODE 1: write split bf16 Chi/Clo (proj).
// MODE 2: exp + causal mask + per-row partial sums -> g_partial; split bf16 out (scores).
// MODE 3: write fp32 C scaled by 1/g_rowsum[row] (pv).
template <int MODE>
__device__ __forceinline__ void gemm_pipe(
    const __nv_bfloat16* __restrict__ Ahi, const __nv_bfloat16* __restrict__ Alo, int lda,
    const __nv_bfloat16* __restrict__ Bhi, const __nv_bfloat16* __restrict__ Blo, int ldb,
    float* __restrict__ C, __nv_bfloat16* __restrict__ Chi, __nv_bfloat16* __restrict__ Clo,
    int ldc, int i0, int j0, int K, int rs_off)
{
    extern __shared__ __align__(16) uint16_t dsm[];
    const uint32_t sb = smem_u32(dsm);

    const int tid  = threadIdx.x;
    const int wid  = tid >> 5;
    const int lane = tid & 31;
    const int m0 = (wid & 1) * 64;
    const int n0 = (wid >> 1) * 32;

    const int a_row = lane & 15;
    const int a_col = (lane >> 4) * 8;
    const int b_row = ((lane >> 4) & 1) * 8 + (lane & 7);
    const int b_col = ((lane >> 3) & 1) * 8;

    const int r0 = tid >> 2,         c0 = (tid & 3) * 8;
    const int r1 = (tid + 256) >> 2, c1 = ((tid + 256) & 3) * 8;

    const __nv_bfloat16* gsrc[4] = {Ahi, Alo, Bhi, Blo};
    const int glda[4] = {lda, lda, ldb, ldb};
    const int grow[4] = {i0, i0, j0, j0};

    const int nk = K >> 5;

    auto stage = [&](int s, int kt) {
#pragma unroll
        for (int b = 0; b < 4; ++b) {
            uint32_t base = sb + (uint32_t)((s * 4 + b) * BUFB);
            const __nv_bfloat16* g = gsrc[b];
            cp16(base + (uint32_t)(r0 * LDSE + c0) * 2,
                 g + (size_t)(grow[b] + r0) * glda[b] + kt + c0);
            cp16(base + (uint32_t)(r1 * LDSE + c1) * 2,
                 g + (size_t)(grow[b] + r1) * glda[b] + kt + c1);
        }
        CP_COMMIT();
    };

    float acc[4][4][4] = {};

    stage(0, 0);
    for (int it = 0; it < nk; ++it) {
        const int s = it & 1;
        if (it + 1 < nk) {
            stage(s ^ 1, (it + 1) << 5);
            CP_WAIT(1);
        } else {
            CP_WAIT(0);
        }
        __syncthreads();

        const uint32_t bAhi = sb + (uint32_t)((s * 4 + 0) * BUFB);
        const uint32_t bAlo = sb + (uint32_t)((s * 4 + 1) * BUFB);
        const uint32_t bBhi = sb + (uint32_t)((s * 4 + 2) * BUFB);
        const uint32_t bBlo = sb + (uint32_t)((s * 4 + 3) * BUFB);

#pragma unroll
        for (int kk = 0; kk < 32; kk += 16) {
            uint32_t aH[4][4], aL[4][4];
#pragma unroll
            for (int mi = 0; mi < 4; ++mi) {
                uint32_t off = (uint32_t)((m0 + mi * 16 + a_row) * LDSE + kk + a_col) * 2;
                ldsm_x4(aH[mi], bAhi + off);
                ldsm_x4(aL[mi], bAlo + off);
            }
#pragma unroll
            for (int nj = 0; nj < 2; ++nj) {
                uint32_t off = (uint32_t)((n0 + nj * 16 + b_row) * LDSE + kk + b_col) * 2;
                uint32_t bh[4], bl[4];
                ldsm_x4(bh, bBhi + off);
                ldsm_x4(bl, bBlo + off);
#pragma unroll
                for (int mi = 0; mi < 4; ++mi) {
                    mma16816(acc[mi][nj * 2],     aH[mi], bh);
                    mma16816(acc[mi][nj * 2 + 1], aH[mi], bh + 2);
                    mma16816(acc[mi][nj * 2],     aH[mi], bl);
                    mma16816(acc[mi][nj * 2 + 1], aH[mi], bl + 2);
                    mma16816(acc[mi][nj * 2],     aL[mi], bh);
                    mma16816(acc[mi][nj * 2 + 1], aL[mi], bh + 2);
                }
            }
        }
        __syncthreads();
    }

    // ---- epilogue ------------------------------------------------------------
    const int tr = lane >> 2;
    const int tc = (lane & 3) * 2;

    if (MODE == 1) {
#pragma unroll
        for (int mi = 0; mi < 4; ++mi)
#pragma unroll
            for (int nj = 0; nj < 4; ++nj) {
                int row = i0 + m0 + mi * 16 + tr;
                int col = j0 + n0 + nj * 8 + tc;
                uint32_t h, l;
                size_t idx = (size_t)row * ldc + col;
                split2(acc[mi][nj][0], acc[mi][nj][1], h, l);
                *reinterpret_cast<uint32_t*>(Chi + idx) = h;
                *reinterpret_cast<uint32_t*>(Clo + idx) = l;
                idx = (size_t)(row + 8) * ldc + col;
                split2(acc[mi][nj][2], acc[mi][nj][3], h, l);
                *reinterpret_cast<uint32_t*>(Chi + idx) = h;
                *reinterpret_cast<uint32_t*>(Clo + idx) = l;
            }
    } else if (MODE == 2) {
        // exp + causal mask + row partial sums (deterministic, no atomics)
        float* red = reinterpret_cast<float*>(dsm);     // 128 rows x 4 n-warps
        const int nwid = wid >> 1;
#pragma unroll
        for (int mi = 0; mi < 4; ++mi) {
#pragma unroll
            for (int rp = 0; rp < 2; ++rp) {
                const int lrow = m0 + mi * 16 + tr + rp * 8;
                const int row  = i0 + lrow;
                float part = 0.f;
#pragma unroll
                for (int nj = 0; nj < 4; ++nj) {
                    int col = j0 + n0 + nj * 8 + tc;
                    float e0 = (col     <= row) ? __expf(acc[mi][nj][rp * 2]     * SM_SCALE) : 0.f;
                    float e1 = (col + 1 <= row) ? __expf(acc[mi][nj][rp * 2 + 1] * SM_SCALE) : 0.f;
                    uint32_t h, l;
                    split2(e0, e1, h, l);
                    size_t idx = (size_t)row * ldc + col;
                    *reinterpret_cast<uint32_t*>(Chi + idx) = h;
                    *reinterpret_cast<uint32_t*>(Clo + idx) = l;
                    part += e0 + e1;
                }
                part += __shfl_xor_sync(0xffffffffu, part, 1);
                part += __shfl_xor_sync(0xffffffffu, part, 2);
                if ((lane & 3) == 0) red[lrow * 4 + nwid] = part;
            }
        }
        __syncthreads();
        if (tid < 128) {
            float s = red[tid * 4] + red[tid * 4 + 1] + red[tid * 4 + 2] + red[tid * 4 + 3];
            g_partial[(size_t)(rs_off + i0 + tid) * 32 + (j0 >> 7)] = s;
        }
    } else {  // MODE 3: pv, normalize by row sums
#pragma unroll
        for (int mi = 0; mi < 4; ++mi) {
            int row = i0 + m0 + mi * 16 + tr;
            float s0 = 1.0f / g_rowsum[rs_off + row];
            float s1 = 1.0f / g_rowsum[rs_off + row + 8];
#pragma unroll
            for (int nj = 0; nj < 4; ++nj) {
                int col = j0 + n0 + nj * 8 + tc;
                *reinterpret_cast<float2*>(C + (size_t)row * ldc + col) =
                    make_float2(acc[mi][nj][0] * s0, acc[mi][nj][1] * s0);
                *reinterpret_cast<float2*>(C + (size_t)(row + 8) * ldc + col) =
                    make_float2(acc[mi][nj][2] * s1, acc[mi][nj][3] * s1);
            }
        }
    }
}

// ---------------- GEMM stage kernels ------------------------------------------
__global__ void __launch_bounds__(256, 2)
proj_tc()
{
    const int z = blockIdx.z;
    const __nv_bfloat16* Bh = g_WThi + (size_t)z * DIM * DIM;
    const __nv_bfloat16* Bl = g_WTlo + (size_t)z * DIM * DIM;
    __nv_bfloat16* Ch = (z == 0) ? g_Qhi : (z == 1) ? g_Khi : g_Vhi;
    __nv_bfloat16* Cl = (z == 0) ? g_Qlo : (z == 1) ? g_Klo : g_Vlo;
    gemm_pipe<1>(g_Xhi, g_Xlo, DIM, Bh, Bl, DIM,
                 nullptr, Ch, Cl, DIM, blockIdx.y * 128, blockIdx.x * 128, DIM, 0);
}

__global__ void __launch_bounds__(256, 2)
scores_tc()
{
    const int i0 = blockIdx.y * 128, j0 = blockIdx.x * 128;
    if (j0 > i0) return;   // fully-masked causal tile
    const size_t off = (size_t)blockIdx.z * SEQ * DIM;
    __nv_bfloat16* Ch = g_Phi + (size_t)blockIdx.z * SEQ * SEQ;
    __nv_bfloat16* Cl = g_Plo + (size_t)blockIdx.z * SEQ * SEQ;
    gemm_pipe<2>(g_Qhi + off, g_Qlo + off, DIM, g_Khi + off, g_Klo + off, DIM,
                 nullptr, Ch, Cl, SEQ, i0, j0, DIM, blockIdx.z * SEQ);
}

__global__ void __launch_bounds__(256, 2)
pv_tc(float* __restrict__ out)
{
    const int i0 = blockIdx.y * 128, j0 = blockIdx.x * 128;
    const size_t poff = (size_t)blockIdx.z * SEQ * SEQ;
    const size_t voff = (size_t)blockIdx.z * DIM * SEQ;
    float* C = out + (size_t)blockIdx.z * SEQ * DIM;
    gemm_pipe<3>(g_Phi + poff, g_Plo + poff, SEQ, g_VThi + voff, g_VTlo + voff, SEQ,
                 C, nullptr, nullptr, DIM, i0, j0, i0 + 128, blockIdx.z * SEQ);
}

// ---------------- rowsum reduce (deterministic) ---------------------------------
__global__ void __launch_bounds__(256)
reduce_rowsum()
{
    const int i = blockIdx.x * 256 + threadIdx.x;   // global token row
    const int q = i & (SEQ - 1);
    const int nt = (q >> 7) + 1;                    // valid tiles for this row
    const float* p = g_partial + (size_t)i * 32;
    float s = 0.f;
    for (int t = 0; t < nt; ++t) s += p[t];
    g_rowsum[i] = s;
}

// ---------------- conversion / transpose kernels -------------------------------
__global__ void conv_x(const float* __restrict__ X)
{
    size_t i = (size_t)blockIdx.x * blockDim.x + threadIdx.x;
    const size_t n4 = (size_t)NTOK * DIM / 4;
    for (; i < n4; i += (size_t)gridDim.x * blockDim.x) {
        float4 v = reinterpret_cast<const float4*>(X)[i];
        uint32_t h0, l0, h1, l1;
        split2(v.x, v.y, h0, l0);
        split2(v.z, v.w, h1, l1);
        reinterpret_cast<uint2*>(g_Xhi)[i] = make_uint2(h0, h1);
        reinterpret_cast<uint2*>(g_Xlo)[i] = make_uint2(l0, l1);
    }
}

__global__ void transpose_w(const float* __restrict__ Wq,
                            const float* __restrict__ Wk,
                            const float* __restrict__ Wv)
{
    const float* src = (blockIdx.z == 0) ? Wq : (blockIdx.z == 1) ? Wk : Wv;
    __nv_bfloat16* dh = g_WThi + (size_t)blockIdx.z * DIM * DIM;
    __nv_bfloat16* dl = g_WTlo + (size_t)blockIdx.z * DIM * DIM;
    __shared__ float t[32][33];
    const int bx = blockIdx.x * 32, by = blockIdx.y * 32;
    const int tx = threadIdx.x, ty = threadIdx.y;
#pragma unroll
    for (int j = 0; j < 32; j += 8)
        t[ty + j][tx] = src[(size_t)(by + ty + j) * DIM + bx + tx];
    __syncthreads();
#pragma unroll
    for (int j = 0; j < 32; j += 8) {
        float v = t[tx][ty + j];
        __nv_bfloat16 h = __float2bfloat16(v);
        size_t idx = (size_t)(bx + ty + j) * DIM + by + tx;
        dh[idx] = h;
        dl[idx] = __float2bfloat16(v - __bfloat162float(h));
    }
}

__global__ void transpose_v()
{
    const int b = blockIdx.z;
    const __nv_bfloat16* sh = g_Vhi + (size_t)b * SEQ * DIM;
    const __nv_bfloat16* sl = g_Vlo + (size_t)b * SEQ * DIM;
    __nv_bfloat16* dh = g_VThi + (size_t)b * DIM * SEQ;
    __nv_bfloat16* dl = g_VTlo + (size_t)b * DIM * SEQ;
    __shared__ float t[32][33];
    const int bx = blockIdx.x * 32, by = blockIdx.y * 32;   // bx over DIM, by over SEQ
    const int tx = threadIdx.x, ty = threadIdx.y;
#pragma unroll
    for (int j = 0; j < 32; j += 8) {
        size_t idx = (size_t)(by + ty + j) * DIM + bx + tx;
        t[ty + j][tx] = __bfloat162float(sh[idx]) + __bfloat162float(sl[idx]);
    }
    __syncthreads();
#pragma unroll
    for (int j = 0; j < 32; j += 8) {
        float v = t[tx][ty + j];
        __nv_bfloat16 h = __float2bfloat16(v);
        size_t idx = (size_t)(bx + ty + j) * SEQ + by + tx;
        dh[idx] = h;
        dl[idx] = __float2bfloat16(v - __bfloat162float(h));
    }
}

// ---------------- launch ---------------------------------------------------------
extern "C" void kernel_launch(void* const* d_in, const int* in_sizes, int n_in,
                              void* d_out, int out_size)
{
    const float* x  = (const float*)d_in[0];
    const float* Wq = (const float*)d_in[1];
    const float* Wk = (const float*)d_in[2];
    const float* Wv = (const float*)d_in[3];
    float* out = (float*)d_out;

    cudaFuncSetAttribute(proj_tc,   cudaFuncAttributeMaxDynamicSharedMemorySize, SMEM_BYTES);
    cudaFuncSetAttribute(scores_tc, cudaFuncAttributeMaxDynamicSharedMemorySize, SMEM_BYTES);
    cudaFuncSetAttribute(pv_tc,     cudaFuncAttributeMaxDynamicSharedMemorySize, SMEM_BYTES);

    dim3 t32(32, 8);
    conv_x<<<512, 256>>>(x);
    transpose_w<<<dim3(DIM / 32, DIM / 32, 3), t32>>>(Wq, Wk, Wv);
    proj_tc<<<dim3(DIM / 128, NTOK / 128, 3), 256, SMEM_BYTES>>>();
    transpose_v<<<dim3(DIM / 32, SEQ / 32, BATCH), t32>>>();
    scores_tc<<<dim3(SEQ / 128, SEQ / 128, BATCH), 256, SMEM_BYTES>>>();
    reduce_rowsum<<<NTOK / 256, 256>>>();
    pv_tc<<<dim3(DIM / 128, SEQ / 128, BATCH), 256, SMEM_BYTES>>>(out);
}